// round 8
// baseline (speedup 1.0000x reference)
#include <cuda_runtime.h>
#include <cuda_fp16.h>
#include <cstdint>

#define NCq   100
#define NCPAD 104
#define NBLKS 128
#define PADH  136      /* Ah / Xh / Wh / Ct stride (halves) */

// ---- static device scratch (no allocations allowed) ----
__device__ __align__(16) float g_Spart[128 * NBLKS];          // [b][kb]
__device__ __align__(16) float g_Opart[128 * NBLKS * NCPAD];  // [b][kb][104]
__device__ int g_bar1 = 0;
__device__ int g_bar2 = 0;

// smem layout (bytes)
#define AH_OFFB  0                                /* 128*136*2 = 34816 */
#define XH_OFFB  34816                            /* 34816 */
#define CT_OFFB  69632                            /* 112*136*2 = 30464 */
#define X2_OFFB  100096                           /* 512 */
#define Y2_OFFB  100608                           /* 512 */
#define SMEM_BYTES 101120
/* Wh (fp16 [b][n], 34816B) aliases the Ah region after GEMM1 */

// ============================ helpers ============================
__device__ __forceinline__ float fsqrt_ap(float x) {
    float r; asm("sqrt.approx.f32 %0, %1;" : "=f"(r) : "f"(x)); return r;
}
__device__ __forceinline__ float frsqrt_ap(float x) {
    float r; asm("rsqrt.approx.f32 %0, %1;" : "=f"(r) : "f"(x)); return r;
}
__device__ __forceinline__ uint2 pack4h(float4 v) {
    __half2 h01 = __floats2half2_rn(v.x, v.y);
    __half2 h23 = __floats2half2_rn(v.z, v.w);
    uint2 u;
    u.x = *(uint32_t*)&h01;
    u.y = *(uint32_t*)&h23;
    return u;
}
// fp16 m16n8k16: D(f32) += A(f16) * B(f16)
__device__ __forceinline__ void mma16(float* d, uint32_t a0, uint32_t a1,
                                      uint32_t a2, uint32_t a3,
                                      uint32_t b0, uint32_t b1) {
    asm volatile(
        "mma.sync.aligned.m16n8k16.row.col.f32.f16.f16.f32 "
        "{%0,%1,%2,%3}, {%4,%5,%6,%7}, {%8,%9}, {%0,%1,%2,%3};"
        : "+f"(d[0]), "+f"(d[1]), "+f"(d[2]), "+f"(d[3])
        : "r"(a0), "r"(a1), "r"(a2), "r"(a3), "r"(b0), "r"(b1));
}

// ============================ main kernel ============================
__global__ __launch_bounds__(512, 1)
void main_kernel(const float* __restrict__ X, const float* __restrict__ A,
                 const float* __restrict__ C, float* __restrict__ out) {
    extern __shared__ __align__(16) char smb[];
    __half* Ah  = (__half*)(smb + AH_OFFB);       // [n][k] fp16, stride PADH
    __half* Xh  = (__half*)(smb + XH_OFFB);       // [b][k] fp16, stride PADH
    __half* Ct  = (__half*)(smb + CT_OFFB);       // [c][n] fp16, stride PADH (c<112)
    float*  x2s = (float*)(smb + X2_OFFB);
    float*  y2s = (float*)(smb + Y2_OFFB);
    __half* Wh  = (__half*)(smb + AH_OFFB);       // later: [b][n] fp16 (aliases Ah)

    const int tid = threadIdx.x;
    const int w   = tid >> 5;        // 0..15
    const int l   = tid & 31;
    const int g   = l >> 2;          // 0..7
    const int tg  = l & 3;           // 0..3
    const int n0  = blockIdx.x * 128;

    // ---------------- load + project + convert (8 iters, 16 rows/iter) ----------------
#pragma unroll
    for (int it = 0; it < 8; it++) {
        const int r = it * 16 + w;
        // A row -> Ah[r][*] (fp16), x2
        float4 va = ((const float4*)(A + (size_t)(n0 + r) * 128))[l];
        float sa = va.x * va.x + va.y * va.y + va.z * va.z + va.w * va.w;
#pragma unroll
        for (int off = 16; off > 0; off >>= 1)
            sa += __shfl_xor_sync(0xffffffffu, sa, off);
        if (l == 0) x2s[r] = sa;
        *(uint2*)&Ah[r * PADH + l * 4] = pack4h(va);

        // X row -> project -> Xh[r][*] (fp16), y2
        float4 vx = ((const float4*)(X + (size_t)r * 128))[l];
        float sx = vx.x * vx.x + vx.y * vx.y + vx.z * vx.z + vx.w * vx.w;
#pragma unroll
        for (int off = 16; off > 0; off >>= 1)
            sx += __shfl_xor_sync(0xffffffffu, sx, off);
        float norm  = fmaxf(sqrtf(sx), 1e-15f);
        const float maxn = 1.0f - 4e-3f;
        float scale = (norm > maxn) ? (maxn / norm) : 1.0f;
        if (l == 0) y2s[r] = sx * scale * scale;
        vx.x *= scale; vx.y *= scale; vx.z *= scale; vx.w *= scale;
        *(uint2*)&Xh[r * PADH + l * 4] = pack4h(vx);

        // C row r -> transposed Ct[c][n=r] (fp16); c=100 gets ones row, 101..111 zero
        if (l < 28) {
            float4 vc = make_float4(0.f, 0.f, 0.f, 0.f);
            if (l < 25)       vc = ((const float4*)(C + (size_t)r * NCq + (size_t)n0 * NCq))[l];
            else if (l == 25) vc = make_float4(1.0f, 0.f, 0.f, 0.f);
            __half h0 = __float2half_rn(vc.x), h1 = __float2half_rn(vc.y);
            __half h2 = __float2half_rn(vc.z), h3 = __float2half_rn(vc.w);
            Ct[(l * 4 + 0) * PADH + r] = h0;
            Ct[(l * 4 + 1) * PADH + r] = h1;
            Ct[(l * 4 + 2) * PADH + r] = h2;
            Ct[(l * 4 + 3) * PADH + r] = h3;
        }
    }
    __syncthreads();

    // ---------------- GEMM1 (fp16): D1[n][b] = A @ Xp^T ----------------
    // 16 warps in 4x4 grid: each warp 32n x 32b
    const int wn = w >> 2, wb = w & 3;
    const __half* Abh = Ah + (wn * 32) * PADH;
    const __half* Xbh = Xh + (wb * 32) * PADH;

    float acc[2][4][4];
#pragma unroll
    for (int mt = 0; mt < 2; mt++)
#pragma unroll
        for (int bt = 0; bt < 4; bt++)
#pragma unroll
            for (int rr = 0; rr < 4; rr++) acc[mt][bt][rr] = 0.f;

#pragma unroll
    for (int ks = 0; ks < 8; ks++) {
        const int k0 = ks * 16 + 2 * tg;
        uint32_t a0[2], a1[2], a2[2], a3[2];
#pragma unroll
        for (int mt = 0; mt < 2; mt++) {
            a0[mt] = *(const uint32_t*)&Abh[(mt * 16 + g)     * PADH + k0];
            a1[mt] = *(const uint32_t*)&Abh[(mt * 16 + 8 + g) * PADH + k0];
            a2[mt] = *(const uint32_t*)&Abh[(mt * 16 + g)     * PADH + k0 + 8];
            a3[mt] = *(const uint32_t*)&Abh[(mt * 16 + 8 + g) * PADH + k0 + 8];
        }
#pragma unroll
        for (int bt = 0; bt < 4; bt++) {
            uint32_t b0 = *(const uint32_t*)&Xbh[(bt * 8 + g) * PADH + k0];
            uint32_t b1 = *(const uint32_t*)&Xbh[(bt * 8 + g) * PADH + k0 + 8];
            mma16(acc[0][bt], a0[0], a1[0], a2[0], a3[0], b0, b1);
            mma16(acc[1][bt], a0[1], a1[1], a2[1], a3[1], b0, b1);
        }
    }

    // ---------------- epilogue: dot -> w ----------------
    // w = (PxPy)^(1/4) * rsqrt(sqrt(den) + sqrt(||x-y||^2))
    float x2v[4], px4[4];
#pragma unroll
    for (int mt = 0; mt < 2; mt++)
#pragma unroll
        for (int h = 0; h < 2; h++) {
            float x2 = x2s[wn * 32 + mt * 16 + h * 8 + g];
            x2v[mt * 2 + h] = x2;
            px4[mt * 2 + h] = fsqrt_ap(fsqrt_ap(1.0f - x2));
        }
    float y2v[8], py4[8];
#pragma unroll
    for (int bt = 0; bt < 4; bt++)
#pragma unroll
        for (int j = 0; j < 2; j++) {
            float y2 = y2s[wb * 32 + bt * 8 + 2 * tg + j];
            y2v[bt * 2 + j] = y2;
            py4[bt * 2 + j] = fsqrt_ap(fsqrt_ap(1.0f - y2));
        }
#pragma unroll
    for (int mt = 0; mt < 2; mt++)
#pragma unroll
        for (int bt = 0; bt < 4; bt++)
#pragma unroll
            for (int rr = 0; rr < 4; rr++) {
                const int hi = rr >> 1, j = rr & 1;
                float dot = acc[mt][bt][rr];
                float x2  = x2v[mt * 2 + hi];
                float y2  = y2v[bt * 2 + j];
                float den = fmaf(x2, y2, fmaf(-2.0f, dot, 1.0f));
                float v2  = fmaxf(fmaf(-2.0f, dot, x2 + y2), 0.0f);
                float s   = fsqrt_ap(den) + fsqrt_ap(v2);
                float wq  = px4[mt * 2 + hi] * py4[bt * 2 + j] * frsqrt_ap(s);
                wq = fminf(fmaxf(wq, 0.015625f), 1.0f);
                acc[mt][bt][rr] = wq;
            }

    __syncthreads();   // all GEMM1 smem reads done before Wh overwrites Ah

    // store W transposed: Wh[b][n] (fp16, aliases Ah region)
#pragma unroll
    for (int mt = 0; mt < 2; mt++)
#pragma unroll
        for (int bt = 0; bt < 4; bt++) {
            const int nn = wn * 32 + mt * 16 + g;
            const int bb = wb * 32 + bt * 8 + 2 * tg;
            Wh[(bb)     * PADH + nn]     = __float2half_rn(acc[mt][bt][0]);
            Wh[(bb + 1) * PADH + nn]     = __float2half_rn(acc[mt][bt][1]);
            Wh[(bb)     * PADH + nn + 8] = __float2half_rn(acc[mt][bt][2]);
            Wh[(bb + 1) * PADH + nn + 8] = __float2half_rn(acc[mt][bt][3]);
        }
    __syncthreads();

    // ---------------- GEMM2 (fp16): O[b][c] = W @ Ct^T  (N=112, col100 = S) ----------------
    // 16 warps in 8x2 grid: each warp 16b x 56c; k = n (128), 8 K-steps
    const int wb2 = w >> 1, wc = w & 1;
    const __half* Wb = Wh + (wb2 * 16) * PADH;

    float acc2[7][4];
#pragma unroll
    for (int ct = 0; ct < 7; ct++)
#pragma unroll
        for (int rr = 0; rr < 4; rr++) acc2[ct][rr] = 0.f;

#pragma unroll
    for (int ks = 0; ks < 8; ks++) {
        const int k0 = ks * 16 + 2 * tg;
        uint32_t a0 = *(const uint32_t*)&Wb[(g)     * PADH + k0];
        uint32_t a1 = *(const uint32_t*)&Wb[(8 + g) * PADH + k0];
        uint32_t a2 = *(const uint32_t*)&Wb[(g)     * PADH + k0 + 8];
        uint32_t a3 = *(const uint32_t*)&Wb[(8 + g) * PADH + k0 + 8];
#pragma unroll
        for (int ct = 0; ct < 7; ct++) {
            const int col = wc * 56 + ct * 8 + g;
            uint32_t b0 = *(const uint32_t*)&Ct[col * PADH + k0];
            uint32_t b1 = *(const uint32_t*)&Ct[col * PADH + k0 + 8];
            mma16(acc2[ct], a0, a1, a2, a3, b0, b1);
        }
    }

    // ---------------- store partials: Opart[b][kb][104], Spart[b][kb] ----------------
    const int kb = blockIdx.x;
#pragma unroll
    for (int ct = 0; ct < 7; ct++) {
        const int c = wc * 56 + ct * 8 + 2 * tg;
        const int b = wb2 * 16 + g;
        if (c < NCq) {
            *(float2*)&g_Opart[((size_t)b * NBLKS + kb) * NCPAD + c] =
                make_float2(acc2[ct][0], acc2[ct][1]);
            *(float2*)&g_Opart[((size_t)(b + 8) * NBLKS + kb) * NCPAD + c] =
                make_float2(acc2[ct][2], acc2[ct][3]);
        } else if (c == NCq) {   // ones column -> softmax denominator
            g_Spart[b * NBLKS + kb]       = acc2[ct][0];
            g_Spart[(b + 8) * NBLKS + kb] = acc2[ct][2];
        }
    }

    // ---------------- grid-wide barrier (all partials visible) ----------------
    __syncthreads();
    if (tid == 0) {
        __threadfence();
        atomicAdd(&g_bar1, 1);
        while (atomicAdd(&g_bar1, 0) < NBLKS) __nanosleep(64);
        __threadfence();
    }
    __syncthreads();

    // ---------------- fused final reduction: block kb handles b = kb ----------------
    {
        __shared__ float2 so[8][52];
        __shared__ float  ssum[8];

        const int b     = blockIdx.x;
        const int split = tid >> 6;      // 0..7
        const int lane  = tid & 63;      // float2 lane: c = 2*lane

        if (lane < 52) {
            float2 o0 = {0.f, 0.f}, o1 = {0.f, 0.f}, o2 = {0.f, 0.f}, o3 = {0.f, 0.f};
            const float2* ob =
                (const float2*)(g_Opart + ((size_t)b * NBLKS + split * 16) * NCPAD) + lane;
#pragma unroll
            for (int i = 0; i < 16; i += 4) {
                float2 v0 = ob[(i + 0) * (NCPAD / 2)];
                float2 v1 = ob[(i + 1) * (NCPAD / 2)];
                float2 v2 = ob[(i + 2) * (NCPAD / 2)];
                float2 v3 = ob[(i + 3) * (NCPAD / 2)];
                o0.x += v0.x; o0.y += v0.y;
                o1.x += v1.x; o1.y += v1.y;
                o2.x += v2.x; o2.y += v2.y;
                o3.x += v3.x; o3.y += v3.y;
            }
            float2 t;
            t.x = (o0.x + o1.x) + (o2.x + o3.x);
            t.y = (o0.y + o1.y) + (o2.y + o3.y);
            so[split][lane] = t;
        }
        if (lane == 0) {
            const float* sb = g_Spart + b * NBLKS + split * 16;
            float s0 = 0.f, s1 = 0.f, s2 = 0.f, s3 = 0.f;
#pragma unroll
            for (int i = 0; i < 16; i += 4) {
                s0 += sb[i + 0]; s1 += sb[i + 1]; s2 += sb[i + 2]; s3 += sb[i + 3];
            }
            ssum[split] = (s0 + s1) + (s2 + s3);
        }
        __syncthreads();

        if (split == 0 && lane < 50) {   // c = 2*lane in [0, 100)
            float2 a0 = so[0][lane], a1 = so[1][lane], a2 = so[2][lane], a3 = so[3][lane];
            float2 a4 = so[4][lane], a5 = so[5][lane], a6 = so[6][lane], a7 = so[7][lane];
            float ox = ((a0.x + a1.x) + (a2.x + a3.x)) + ((a4.x + a5.x) + (a6.x + a7.x));
            float oy = ((a0.y + a1.y) + (a2.y + a3.y)) + ((a4.y + a5.y) + (a6.y + a7.y));
            float st = ((ssum[0] + ssum[1]) + (ssum[2] + ssum[3]))
                     + ((ssum[4] + ssum[5]) + (ssum[6] + ssum[7]));
            float inv = 1.0f / st;
            *(float2*)(out + b * NCq + 2 * lane) = make_float2(ox * inv, oy * inv);
        }
    }

    // ---------------- reset barrier counters for next replay ----------------
    __syncthreads();
    if (tid == 0) {
        int old = atomicAdd(&g_bar2, 1);
        if (old == NBLKS - 1) {         // last block: everyone passed bar1 & finished
            atomicExch(&g_bar1, 0);
            atomicExch(&g_bar2, 0);
        }
    }
}

// ============================ launch ============================
extern "C" void kernel_launch(void* const* d_in, const int* in_sizes, int n_in,
                              void* d_out, int out_size) {
    (void)in_sizes; (void)n_in; (void)out_size;
    const float* X = (const float*)d_in[0];   // [128,128]
    const float* A = (const float*)d_in[1];   // [16384,1,128]
    const float* C = (const float*)d_in[2];   // [16384,100]
    float* out = (float*)d_out;               // [128,100] fp32

    cudaFuncSetAttribute(main_kernel,
                         cudaFuncAttributeMaxDynamicSharedMemorySize, SMEM_BYTES);

    main_kernel<<<NBLKS, 512, SMEM_BYTES>>>(X, A, C, out);
}

// round 9
// speedup vs baseline: 1.0042x; 1.0042x over previous
#include <cuda_runtime.h>
#include <cuda_fp16.h>
#include <cstdint>

#define NCq   100
#define NCPAD 104
#define NBLKS 128
#define PADH  136      /* Ah / Xh / Wh / Ct stride (halves) */

// ---- static device scratch (no allocations allowed) ----
__device__ __align__(16) float g_Spart[128 * NBLKS];          // [b][kb]
__device__ __align__(16) float g_Opart[128 * NBLKS * NCPAD];  // [b][kb][104]
__device__ int g_bar1 = 0;
__device__ int g_bar2 = 0;

// smem layout (bytes)
#define AH_OFFB  0                                /* 128*136*2 = 34816 */
#define XH_OFFB  34816                            /* 34816 */
#define CT_OFFB  69632                            /* 128*136*2 = 34816 */
#define X2_OFFB  104448                           /* 512 */
#define Y2_OFFB  104960                           /* 512 */
#define SMEM_BYTES 105472
/* Wh (fp16 [b][n]) aliases Ah after GEMM1; reduce scratch aliases Ah after GEMM2 */

// ============================ helpers ============================
__device__ __forceinline__ float fsqrt_ap(float x) {
    float r; asm("sqrt.approx.f32 %0, %1;" : "=f"(r) : "f"(x)); return r;
}
__device__ __forceinline__ float frsqrt_ap(float x) {
    float r; asm("rsqrt.approx.f32 %0, %1;" : "=f"(r) : "f"(x)); return r;
}
__device__ __forceinline__ uint2 pack4h(float4 v) {
    __half2 h01 = __floats2half2_rn(v.x, v.y);
    __half2 h23 = __floats2half2_rn(v.z, v.w);
    uint2 u;
    u.x = *(uint32_t*)&h01;
    u.y = *(uint32_t*)&h23;
    return u;
}
// fp16 m16n8k16: D(f32) += A(f16) * B(f16)
__device__ __forceinline__ void mma16(float* d, uint32_t a0, uint32_t a1,
                                      uint32_t a2, uint32_t a3,
                                      uint32_t b0, uint32_t b1) {
    asm volatile(
        "mma.sync.aligned.m16n8k16.row.col.f32.f16.f16.f32 "
        "{%0,%1,%2,%3}, {%4,%5,%6,%7}, {%8,%9}, {%0,%1,%2,%3};"
        : "+f"(d[0]), "+f"(d[1]), "+f"(d[2]), "+f"(d[3])
        : "r"(a0), "r"(a1), "r"(a2), "r"(a3), "r"(b0), "r"(b1));
}

// ============================ main kernel ============================
__global__ __launch_bounds__(1024, 1)
void main_kernel(const float* __restrict__ X, const float* __restrict__ A,
                 const float* __restrict__ C, float* __restrict__ out) {
    extern __shared__ __align__(16) char smb[];
    __half* Ah  = (__half*)(smb + AH_OFFB);       // [n][k] fp16, stride PADH
    __half* Xh  = (__half*)(smb + XH_OFFB);       // [b][k] fp16, stride PADH
    __half* Ct  = (__half*)(smb + CT_OFFB);       // [c][n] fp16, stride PADH (c<128)
    float*  x2s = (float*)(smb + X2_OFFB);
    float*  y2s = (float*)(smb + Y2_OFFB);
    __half* Wh  = (__half*)(smb + AH_OFFB);       // later: [b][n] fp16 (aliases Ah)

    const int tid = threadIdx.x;
    const int w   = tid >> 5;        // 0..31
    const int l   = tid & 31;
    const int g   = l >> 2;          // 0..7
    const int tg  = l & 3;           // 0..3
    const int n0  = blockIdx.x * 128;

    // ---------------- load + project + convert (4 iters, 32 rows/iter) ----------------
#pragma unroll
    for (int it = 0; it < 4; it++) {
        const int r = it * 32 + w;
        // A row -> Ah[r][*] (fp16), x2
        float4 va = ((const float4*)(A + (size_t)(n0 + r) * 128))[l];
        float sa = va.x * va.x + va.y * va.y + va.z * va.z + va.w * va.w;
#pragma unroll
        for (int off = 16; off > 0; off >>= 1)
            sa += __shfl_xor_sync(0xffffffffu, sa, off);
        if (l == 0) x2s[r] = sa;
        *(uint2*)&Ah[r * PADH + l * 4] = pack4h(va);

        // X row -> project -> Xh[r][*] (fp16), y2
        float4 vx = ((const float4*)(X + (size_t)r * 128))[l];
        float sx = vx.x * vx.x + vx.y * vx.y + vx.z * vx.z + vx.w * vx.w;
#pragma unroll
        for (int off = 16; off > 0; off >>= 1)
            sx += __shfl_xor_sync(0xffffffffu, sx, off);
        float norm  = fmaxf(sqrtf(sx), 1e-15f);
        const float maxn = 1.0f - 4e-3f;
        float scale = (norm > maxn) ? (maxn / norm) : 1.0f;
        if (l == 0) y2s[r] = sx * scale * scale;
        vx.x *= scale; vx.y *= scale; vx.z *= scale; vx.w *= scale;
        *(uint2*)&Xh[r * PADH + l * 4] = pack4h(vx);

        // C row (n0+r) -> transposed Ct[c][n=r] (fp16); c=100 ones, 101..127 zero
        {
            float4 vc = make_float4(0.f, 0.f, 0.f, 0.f);
            if (l < 25)       vc = ((const float4*)(C + (size_t)(n0 + r) * NCq))[l];
            else if (l == 25) vc = make_float4(1.0f, 0.f, 0.f, 0.f);
            Ct[(l * 4 + 0) * PADH + r] = __float2half_rn(vc.x);
            Ct[(l * 4 + 1) * PADH + r] = __float2half_rn(vc.y);
            Ct[(l * 4 + 2) * PADH + r] = __float2half_rn(vc.z);
            Ct[(l * 4 + 3) * PADH + r] = __float2half_rn(vc.w);
        }
    }
    __syncthreads();

    // ---------------- GEMM1 (fp16): D1[n][b] = A @ Xp^T ----------------
    // 32 warps in 8x4 grid: each warp 16n x 32b
    const int wn = w >> 2, wb = w & 3;
    const __half* Abh = Ah + (wn * 16) * PADH;
    const __half* Xbh = Xh + (wb * 32) * PADH;

    float acc[4][4];
#pragma unroll
    for (int bt = 0; bt < 4; bt++)
#pragma unroll
        for (int rr = 0; rr < 4; rr++) acc[bt][rr] = 0.f;

#pragma unroll
    for (int ks = 0; ks < 8; ks++) {
        const int k0 = ks * 16 + 2 * tg;
        uint32_t a0 = *(const uint32_t*)&Abh[(g)     * PADH + k0];
        uint32_t a1 = *(const uint32_t*)&Abh[(8 + g) * PADH + k0];
        uint32_t a2 = *(const uint32_t*)&Abh[(g)     * PADH + k0 + 8];
        uint32_t a3 = *(const uint32_t*)&Abh[(8 + g) * PADH + k0 + 8];
#pragma unroll
        for (int bt = 0; bt < 4; bt++) {
            uint32_t b0 = *(const uint32_t*)&Xbh[(bt * 8 + g) * PADH + k0];
            uint32_t b1 = *(const uint32_t*)&Xbh[(bt * 8 + g) * PADH + k0 + 8];
            mma16(acc[bt], a0, a1, a2, a3, b0, b1);
        }
    }

    // ---------------- epilogue: dot -> w ----------------
    // w = (PxPy)^(1/4) * rsqrt(sqrt(den) + sqrt(||x-y||^2))
    float x2v[2], px4[2];
#pragma unroll
    for (int h = 0; h < 2; h++) {
        float x2 = x2s[wn * 16 + h * 8 + g];
        x2v[h] = x2;
        px4[h] = fsqrt_ap(fsqrt_ap(1.0f - x2));
    }
    float y2v[8], py4[8];
#pragma unroll
    for (int bt = 0; bt < 4; bt++)
#pragma unroll
        for (int j = 0; j < 2; j++) {
            float y2 = y2s[wb * 32 + bt * 8 + 2 * tg + j];
            y2v[bt * 2 + j] = y2;
            py4[bt * 2 + j] = fsqrt_ap(fsqrt_ap(1.0f - y2));
        }
#pragma unroll
    for (int bt = 0; bt < 4; bt++)
#pragma unroll
        for (int rr = 0; rr < 4; rr++) {
            const int hi = rr >> 1, j = rr & 1;
            float dot = acc[bt][rr];
            float x2  = x2v[hi];
            float y2  = y2v[bt * 2 + j];
            float den = fmaf(x2, y2, fmaf(-2.0f, dot, 1.0f));
            float v2  = fmaxf(fmaf(-2.0f, dot, x2 + y2), 0.0f);
            float s   = fsqrt_ap(den) + fsqrt_ap(v2);
            float wq  = px4[hi] * py4[bt * 2 + j] * frsqrt_ap(s);
            wq = fminf(fmaxf(wq, 0.015625f), 1.0f);
            acc[bt][rr] = wq;
        }

    __syncthreads();   // all GEMM1 smem reads done before Wh overwrites Ah

    // store W transposed: Wh[b][n] (fp16, aliases Ah region)
#pragma unroll
    for (int bt = 0; bt < 4; bt++) {
        const int nn = wn * 16 + g;
        const int bb = wb * 32 + bt * 8 + 2 * tg;
        Wh[(bb)     * PADH + nn]     = __float2half_rn(acc[bt][0]);
        Wh[(bb + 1) * PADH + nn]     = __float2half_rn(acc[bt][1]);
        Wh[(bb)     * PADH + nn + 8] = __float2half_rn(acc[bt][2]);
        Wh[(bb + 1) * PADH + nn + 8] = __float2half_rn(acc[bt][3]);
    }
    __syncthreads();

    // ---------------- GEMM2 (fp16): O[b][c] = W @ Ct^T  (c padded to 128, col100 = S) ----------------
    // 32 warps in 8x4 grid: each warp 16b x 32c; k = n (128), 8 K-steps
    const int wb2 = w >> 2, wc = w & 3;
    const __half* Wb = Wh + (wb2 * 16) * PADH;

    float acc2[4][4];
#pragma unroll
    for (int ct = 0; ct < 4; ct++)
#pragma unroll
        for (int rr = 0; rr < 4; rr++) acc2[ct][rr] = 0.f;

#pragma unroll
    for (int ks = 0; ks < 8; ks++) {
        const int k0 = ks * 16 + 2 * tg;
        uint32_t a0 = *(const uint32_t*)&Wb[(g)     * PADH + k0];
        uint32_t a1 = *(const uint32_t*)&Wb[(8 + g) * PADH + k0];
        uint32_t a2 = *(const uint32_t*)&Wb[(g)     * PADH + k0 + 8];
        uint32_t a3 = *(const uint32_t*)&Wb[(8 + g) * PADH + k0 + 8];
#pragma unroll
        for (int ct = 0; ct < 4; ct++) {
            const int col = wc * 32 + ct * 8 + g;
            uint32_t b0 = *(const uint32_t*)&Ct[col * PADH + k0];
            uint32_t b1 = *(const uint32_t*)&Ct[col * PADH + k0 + 8];
            mma16(acc2[ct], a0, a1, a2, a3, b0, b1);
        }
    }

    // ---------------- store partials: Opart[b][kb][104], Spart[b][kb] ----------------
    const int kb = blockIdx.x;
#pragma unroll
    for (int ct = 0; ct < 4; ct++) {
        const int c = wc * 32 + ct * 8 + 2 * tg;
        const int b = wb2 * 16 + g;
        if (c < NCq) {
            *(float2*)&g_Opart[((size_t)b * NBLKS + kb) * NCPAD + c] =
                make_float2(acc2[ct][0], acc2[ct][1]);
            *(float2*)&g_Opart[((size_t)(b + 8) * NBLKS + kb) * NCPAD + c] =
                make_float2(acc2[ct][2], acc2[ct][3]);
        } else if (c == NCq) {   // ones column -> softmax denominator
            g_Spart[b * NBLKS + kb]       = acc2[ct][0];
            g_Spart[(b + 8) * NBLKS + kb] = acc2[ct][2];
        }
    }

    // ---------------- grid-wide barrier (all partials visible) ----------------
    __syncthreads();
    if (tid == 0) {
        __threadfence();
        atomicAdd(&g_bar1, 1);
        while (atomicAdd(&g_bar1, 0) < NBLKS) __nanosleep(64);
        __threadfence();
    }
    __syncthreads();

    // ---------------- fused final reduction: block kb handles b = kb ----------------
    {
        float2* so   = (float2*)smb;            // [16][52] float2 (aliases Ah, free now)
        float*  ssum = (float*)(smb + 16 * 52 * sizeof(float2));  // [16]

        const int b     = blockIdx.x;
        const int split = tid >> 6;      // 0..15
        const int lane  = tid & 63;      // float2 lane: c = 2*lane

        if (lane < 52) {
            float2 o0 = {0.f, 0.f}, o1 = {0.f, 0.f};
            float2 o2 = {0.f, 0.f}, o3 = {0.f, 0.f};
            const float2* ob =
                (const float2*)(g_Opart + ((size_t)b * NBLKS + split * 8) * NCPAD) + lane;
#pragma unroll
            for (int i = 0; i < 8; i += 4) {
                float2 v0 = ob[(i + 0) * (NCPAD / 2)];
                float2 v1 = ob[(i + 1) * (NCPAD / 2)];
                float2 v2 = ob[(i + 2) * (NCPAD / 2)];
                float2 v3 = ob[(i + 3) * (NCPAD / 2)];
                o0.x += v0.x; o0.y += v0.y;
                o1.x += v1.x; o1.y += v1.y;
                o2.x += v2.x; o2.y += v2.y;
                o3.x += v3.x; o3.y += v3.y;
            }
            float2 t;
            t.x = (o0.x + o1.x) + (o2.x + o3.x);
            t.y = (o0.y + o1.y) + (o2.y + o3.y);
            so[split * 52 + lane] = t;
        }
        if (lane == 0) {
            const float* sb = g_Spart + b * NBLKS + split * 8;
            float s0 = 0.f, s1 = 0.f;
#pragma unroll
            for (int i = 0; i < 8; i += 2) { s0 += sb[i]; s1 += sb[i + 1]; }
            ssum[split] = s0 + s1;
        }
        __syncthreads();

        if (split == 0 && lane < 50) {   // c = 2*lane in [0, 100)
            float ox = 0.f, oy = 0.f, st = 0.f;
#pragma unroll
            for (int s2 = 0; s2 < 16; s2++) {
                float2 a = so[s2 * 52 + lane];
                ox += a.x; oy += a.y;
                st += ssum[s2];
            }
            float inv = 1.0f / st;
            *(float2*)(out + b * NCq + 2 * lane) = make_float2(ox * inv, oy * inv);
        }
    }

    // ---------------- reset barrier counters for next replay ----------------
    __syncthreads();
    if (tid == 0) {
        int old = atomicAdd(&g_bar2, 1);
        if (old == NBLKS - 1) {         // last block: everyone passed bar1 & finished
            atomicExch(&g_bar1, 0);
            atomicExch(&g_bar2, 0);
        }
    }
}

// ============================ launch ============================
extern "C" void kernel_launch(void* const* d_in, const int* in_sizes, int n_in,
                              void* d_out, int out_size) {
    (void)in_sizes; (void)n_in; (void)out_size;
    const float* X = (const float*)d_in[0];   // [128,128]
    const float* A = (const float*)d_in[1];   // [16384,1,128]
    const float* C = (const float*)d_in[2];   // [16384,100]
    float* out = (float*)d_out;               // [128,100] fp32

    cudaFuncSetAttribute(main_kernel,
                         cudaFuncAttributeMaxDynamicSharedMemorySize, SMEM_BYTES);

    main_kernel<<<NBLKS, 1024, SMEM_BYTES>>>(X, A, C, out);
}